// round 2
// baseline (speedup 1.0000x reference)
#include <cuda_runtime.h>
#include <math.h>

// Problem constants
#define M0_ 16
#define M1_ 8
#define Q0_ 8
#define Q1_ 4
#define O0_ 16
#define O1_ 8

#define N_MAX 10000
#define E_MAX 100000

// Scratch (no cudaMalloc allowed)
__device__ float g_q[N_MAX * 20];        // per-node q: 8 scalar + 4*3 vector
__device__ float g_z[N_MAX];             // softmax denominator
__device__ float g_ex[E_MAX];            // per-edge exp(dot)
__device__ float g_v[(size_t)E_MAX * 40];// per-edge v: 16 scalar + 8*3 vector

// ---------------------------------------------------------------------------
// Kernel 0: per-node q projection, zero z and out
// ---------------------------------------------------------------------------
__global__ void k_nodes(const float* __restrict__ node_ft,
                        const float* __restrict__ wqs,   // [16,8]
                        const float* __restrict__ wqv,   // [8,4]
                        float* __restrict__ out, int N)
{
    int n = blockIdx.x * blockDim.x + threadIdx.x;
    if (n >= N) return;
    const float* x = node_ft + (size_t)n * 40;
    float xs[16], xv[24];
#pragma unroll
    for (int i = 0; i < 16; i++) xs[i] = x[i];
#pragma unroll
    for (int i = 0; i < 24; i++) xv[i] = x[16 + i];

    const float s0 = 0.25f;                   // 1/sqrt(16)
    const float s1 = 0.35355339059327373f;    // 1/sqrt(8)
    float q[20];
#pragma unroll
    for (int o = 0; o < 8; o++) {
        float acc = 0.f;
#pragma unroll
        for (int i = 0; i < 16; i++) acc += xs[i] * wqs[i * 8 + o];
        q[o] = acc * s0;
    }
#pragma unroll
    for (int o = 0; o < 4; o++) {
#pragma unroll
        for (int c = 0; c < 3; c++) {
            float acc = 0.f;
#pragma unroll
            for (int i = 0; i < 8; i++) acc += xv[i * 3 + c] * wqv[i * 4 + o];
            q[8 + o * 3 + c] = acc * s1;
        }
    }
#pragma unroll
    for (int i = 0; i < 20; i++) g_q[(size_t)n * 20 + i] = q[i];
    g_z[n] = 0.f;
#pragma unroll
    for (int i = 0; i < 40; i++) out[(size_t)n * 40 + i] = 0.f;
}

// ---------------------------------------------------------------------------
// Kernel 1: per-edge main work.
//   Block = 256 threads handles 8 edges.
//   Phase 1: hidden activations h_k[32], h_v[32] per edge (silu MLP layer 1)
//   Phase 2: register-blocked weight-gen  w = h @ W2 / sqrt(32)  -> smem
//   Phase 3: warp-per-edge CG contraction -> k, v; dot with q[recv]; exp; atomic z
// ---------------------------------------------------------------------------
__global__ void __launch_bounds__(256) k_edges(
    const float* __restrict__ node_ft,
    const int* __restrict__ eidx,            // [2,E] int32 (JAX default: x64 off)
    const float* __restrict__ edge_sh,       // [E,4]
    const float* __restrict__ edge_sc,       // [E,16]
    const float* __restrict__ fck_w1,        // [16,32]
    const float* __restrict__ fck_w2,        // [32,320]
    const float* __restrict__ fcv_w1,        // [16,32]
    const float* __restrict__ fcv_w2,        // [32,640]
    const float* __restrict__ wdot_s,        // [8,8]
    const float* __restrict__ wdot_v,        // [4,4]
    int E)
{
    __shared__ float sh_h[8][64];     // [edge][ h_k(0..31) | h_v(32..63) ]
    __shared__ float sh_wk[8][320];
    __shared__ float sh_wv[8][640];
    __shared__ float sh_p[8][96];     // XS@0(16) XV@16(24) SHS@40 SHV@41(3) PSS@44(16) PVV@60(8) PXX@68(24)
    __shared__ float sh_k[8][20];     // k_s(8) + k_v(12)

    const int tid   = threadIdx.x;
    const int ebase = blockIdx.x * 8;

    // ---- Phase 1: hidden activations (512 tasks) ----
    for (int task = tid; task < 512; task += 256) {
        int e  = task >> 6;
        int jj = task & 63;
        int eg = min(ebase + e, E - 1);
        const float* es = edge_sc + (size_t)eg * 16;
        const float* W1 = (jj < 32) ? fck_w1 : fcv_w1;
        int j = jj & 31;
        float acc = 0.f;
#pragma unroll
        for (int i = 0; i < 16; i++) acc += es[i] * W1[i * 32 + j];
        acc *= 0.25f;                               // 1/sqrt(16)
        sh_h[e][jj] = acc / (1.f + expf(-acc));     // silu
    }
    __syncthreads();

    // ---- Phase 2: weight generation, register-blocked over 8 edges ----
    const float isq32 = 0.17677669529663687f;       // 1/sqrt(32)
    if (tid < 240) {
        const float* W2; int col, ncol, hoff;
        if (tid < 80) { W2 = fck_w2; col = tid * 4;        ncol = 320; hoff = 0;  }
        else          { W2 = fcv_w2; col = (tid - 80) * 4; ncol = 640; hoff = 32; }
        float4 acc[8];
#pragma unroll
        for (int e = 0; e < 8; e++) acc[e] = make_float4(0.f, 0.f, 0.f, 0.f);
        for (int j = 0; j < 32; j++) {
            float4 w = *reinterpret_cast<const float4*>(W2 + (size_t)j * ncol + col);
#pragma unroll
            for (int e = 0; e < 8; e++) {
                float h = sh_h[e][hoff + j];
                acc[e].x += h * w.x; acc[e].y += h * w.y;
                acc[e].z += h * w.z; acc[e].w += h * w.w;
            }
        }
#pragma unroll
        for (int e = 0; e < 8; e++) {
            float4 r = acc[e];
            r.x *= isq32; r.y *= isq32; r.z *= isq32; r.w *= isq32;
            if (tid < 80) *reinterpret_cast<float4*>(&sh_wk[e][col]) = r;
            else          *reinterpret_cast<float4*>(&sh_wv[e][col]) = r;
        }
    }
    __syncthreads();

    // ---- Phase 3: warp per edge ----
    const int wid  = tid >> 5;
    const int lane = tid & 31;
    const int eg   = ebase + wid;
    const bool active = (eg < E);
    const int egc  = min(eg, E - 1);
    const int snd = eidx[egc];
    const int rcv = eidx[E + egc];
    const float* nf = node_ft + (size_t)snd * 40;
    const float shs  = edge_sh[(size_t)egc * 4 + 0];
    const float shv0 = edge_sh[(size_t)egc * 4 + 1];
    const float shv1 = edge_sh[(size_t)egc * 4 + 2];
    const float shv2 = edge_sh[(size_t)egc * 4 + 3];
    float* P = sh_p[wid];

    if (lane < 16) {
        float xs = nf[lane];
        P[lane]      = xs;
        P[44 + lane] = xs * shs;                    // p_ss
    } else if (lane < 24) {
        int i = lane - 16;
        float v0 = nf[16 + i * 3 + 0];
        float v1 = nf[16 + i * 3 + 1];
        float v2 = nf[16 + i * 3 + 2];
        P[16 + i * 3 + 0] = v0; P[16 + i * 3 + 1] = v1; P[16 + i * 3 + 2] = v2;
        P[60 + i] = (v0 * shv0 + v1 * shv1 + v2 * shv2) * 0.5773502691896258f; // p_vv /sqrt3
        const float is2 = 0.7071067811865476f;      // 1/sqrt(2)
        P[68 + i * 3 + 0] = (v1 * shv2 - v2 * shv1) * is2;   // cross(xv, shv)/sqrt2
        P[68 + i * 3 + 1] = (v2 * shv0 - v0 * shv2) * is2;
        P[68 + i * 3 + 2] = (v0 * shv1 - v1 * shv0) * is2;
    } else if (lane == 24) {
        P[40] = shs; P[41] = shv0; P[42] = shv1; P[43] = shv2;
    }
    __syncwarp();

    const float* WK = sh_wk[wid];
    const float* WV = sh_wv[wid];
    float* K = sh_k[wid];
    const float isq24 = 0.2041241452319315f;        // 1/sqrt(24)

    // k_s (lanes 0..7), k_v (lanes 8..19)
    if (lane < 8) {
        int o = lane;
        float acc = 0.f;
#pragma unroll
        for (int i = 0; i < 16; i++) acc += P[44 + i] * WK[i * 8 + o];
#pragma unroll
        for (int i = 0; i < 8;  i++) acc += P[60 + i] * WK[128 + i * 8 + o];
        K[o] = acc * isq24;
    } else if (lane < 20) {
        int t = lane - 8; int o = t / 3; int c = t % 3;
        float a = 0.f, b = 0.f, cx = 0.f;
#pragma unroll
        for (int i = 0; i < 16; i++) a  += P[i]            * WK[192 + i * 4 + o];
#pragma unroll
        for (int i = 0; i < 8;  i++) b  += P[16 + i * 3 + c] * WK[256 + i * 4 + o];
#pragma unroll
        for (int i = 0; i < 8;  i++) cx += P[68 + i * 3 + c] * WK[288 + i * 4 + o];
        K[8 + t] = (P[41 + c] * a + P[40] * b + cx) * isq32;
    }

    // v_s (lanes 0..15)
    if (lane < 16) {
        int o = lane;
        float acc = 0.f;
#pragma unroll
        for (int i = 0; i < 16; i++) acc += P[44 + i] * WV[i * 16 + o];
#pragma unroll
        for (int i = 0; i < 8;  i++) acc += P[60 + i] * WV[256 + i * 16 + o];
        if (active) g_v[(size_t)eg * 40 + o] = acc * isq24;
    }
    // v_v: 24 comps. lanes 16..31 -> t=0..15, lanes 0..7 -> t=16..23
    {
        int t = (lane >= 16) ? (lane - 16) : (lane + 16);
        if (t < 24) {
            int o = t / 3, c = t % 3;
            float a = 0.f, b = 0.f, cx = 0.f;
#pragma unroll
            for (int i = 0; i < 16; i++) a  += P[i]            * WV[384 + i * 8 + o];
#pragma unroll
            for (int i = 0; i < 8;  i++) b  += P[16 + i * 3 + c] * WV[512 + i * 8 + o];
#pragma unroll
            for (int i = 0; i < 8;  i++) cx += P[68 + i * 3 + c] * WV[576 + i * 8 + o];
            float vv = (P[41 + c] * a + P[40] * b + cx) * isq32;
            if (active) g_v[(size_t)eg * 40 + 16 + t] = vv;
        }
    }
    __syncwarp();

    // dot(q[recv], k)
    const float* qr = g_q + (size_t)rcv * 20;
    float d = 0.f;
    {
        int term = lane;
        int i = term >> 3, j = term & 7;
        d += qr[i] * K[j] * wdot_s[i * 8 + j];
        term += 32; i = term >> 3; j = term & 7;
        d += qr[i] * K[j] * wdot_s[i * 8 + j];
    }
    if (lane < 16) {
        int i = lane >> 2, j = lane & 3;
        float s = qr[8 + i * 3 + 0] * K[8 + j * 3 + 0]
                + qr[8 + i * 3 + 1] * K[8 + j * 3 + 1]
                + qr[8 + i * 3 + 2] * K[8 + j * 3 + 2];
        d += s * wdot_v[i * 4 + j] * 0.5773502691896258f;   // 1/sqrt(3)
    }
#pragma unroll
    for (int off = 16; off; off >>= 1) d += __shfl_xor_sync(0xffffffffu, d, off);
    if (lane == 0 && active) {
        d *= 0.11180339887498948f;                 // 1/sqrt(80)
        float ex = expf(d);
        g_ex[eg] = ex;
        atomicAdd(&g_z[rcv], ex);
    }
}

// ---------------------------------------------------------------------------
// Kernel 2: softmax-normalize and scatter-add to output
// ---------------------------------------------------------------------------
__global__ void k_scatter(const int* __restrict__ eidx,
                          float* __restrict__ out, int E)
{
    int idx = blockIdx.x * blockDim.x + threadIdx.x;
    int e = idx / 40;
    int c = idx % 40;
    if (e >= E) return;
    int rcv = eidx[E + e];
    float a = sqrtf(g_ex[e] / g_z[rcv]);
    atomicAdd(&out[(size_t)rcv * 40 + c], a * g_v[(size_t)e * 40 + c]);
}

// ---------------------------------------------------------------------------
extern "C" void kernel_launch(void* const* d_in, const int* in_sizes, int n_in,
                              void* d_out, int out_size)
{
    const float* node_ft = (const float*)d_in[0];
    const int*   eidx    = (const int*)d_in[1];
    const float* edge_sh = (const float*)d_in[2];
    const float* edge_sc = (const float*)d_in[3];
    const float* wqs     = (const float*)d_in[4];
    const float* wqv     = (const float*)d_in[5];
    const float* fck_w1  = (const float*)d_in[6];
    const float* fck_w2  = (const float*)d_in[7];
    const float* fcv_w1  = (const float*)d_in[8];
    const float* fcv_w2  = (const float*)d_in[9];
    const float* wdot_s  = (const float*)d_in[10];
    const float* wdot_v  = (const float*)d_in[11];
    float* out = (float*)d_out;

    int N = in_sizes[0] / 40;
    int E = in_sizes[1] / 2;

    k_nodes<<<(N + 255) / 256, 256>>>(node_ft, wqs, wqv, out, N);
    k_edges<<<(E + 7) / 8, 256>>>(node_ft, eidx, edge_sh, edge_sc,
                                  fck_w1, fck_w2, fcv_w1, fcv_w2,
                                  wdot_s, wdot_v, E);
    k_scatter<<<((long long)E * 40 + 255) / 256, 256>>>(eidx, out, E);
}